// round 7
// baseline (speedup 1.0000x reference)
#include <cuda_runtime.h>
#include <stdint.h>

// ---------------------------------------------------------------------------
// TripletContrastiveLoss — tf32 mma.sync + cp.async double-buffered pipeline.
// (tcgen05 unavailable: bench PTX stage targets compute_103 w/o 'a' suffix.)
// ---------------------------------------------------------------------------

#define BMAX 8192
#define DMAX 1024
#define INFBITS 0x7f800000u

#define BM 256
#define BN 128
#define BK 32
#define ASTR 36   // smem row stride (floats); (4*qid+qlane)%32 distinct -> no conflicts
#define NTHR 512

__device__ float g_A[(size_t)BMAX * DMAX];   // normalized anchors (tf32-rounded)
__device__ float g_F[(size_t)BMAX * DMAX];   // normalized fields  (tf32-rounded)
__device__ int   g_aRow[BMAX];
__device__ int   g_fRow[BMAX];
__device__ int   g_aLab[BMAX];
__device__ int   g_fLab[BMAX];
__device__ int   g_aCnt;
__device__ int   g_fCnt;
__device__ unsigned g_posBits[BMAX];
__device__ unsigned g_negBits[BMAX];
__device__ int   g_is64;

__device__ __forceinline__ uint32_t smem_u32(const void* p) {
    uint32_t a;
    asm("{ .reg .u64 t; cvta.to.shared.u64 t, %1; cvt.u32.u64 %0, t; }"
        : "=r"(a) : "l"(p));
    return a;
}
__device__ __forceinline__ void cpa16(uint32_t dst, const void* src) {
    asm volatile("cp.async.cg.shared.global [%0], [%1], 16;"
                 :: "r"(dst), "l"(src));
}
__device__ __forceinline__ void cpa_commit() {
    asm volatile("cp.async.commit_group;");
}

// ---- K0: reset scalars --------------------------------------------------
__global__ void k0_reset() {
    g_aCnt = 0;
    g_fCnt = 0;
    g_is64 = 1;
}

// ---- K1: init min arrays + label dtype detection ------------------------
__global__ void k1_init_detect(const unsigned* __restrict__ labw, int B) {
    int i = blockIdx.x * blockDim.x + threadIdx.x;
    if (i < B) {
        g_posBits[i] = INFBITS;
        g_negBits[i] = INFBITS;
        if ((i & 1) && labw[i] != 0u) g_is64 = 0;
    }
}

// ---- K2: partition into compact anchor/field lists ----------------------
__global__ void k2_partition(const void* __restrict__ labels,
                             const void* __restrict__ doms, int B) {
    int i = blockIdx.x * blockDim.x + threadIdx.x;
    if (i >= B) return;
    int is64 = g_is64;
    long long dom, lab;
    if (is64) {
        dom = ((const long long*)doms)[i];
        lab = ((const long long*)labels)[i];
    } else {
        dom = ((const int*)doms)[i];
        lab = ((const int*)labels)[i];
    }
    if (dom == 0) {
        int p = atomicAdd(&g_aCnt, 1);
        g_aRow[p] = i;
        g_aLab[p] = (int)lab;
    } else if (dom == 1) {
        int p = atomicAdd(&g_fCnt, 1);
        g_fRow[p] = i;
        g_fLab[p] = (int)lab;
    }
}

// ---- K3: normalize + tf32 round, one warp per row ------------------------
__global__ void k3_normalize(const float* __restrict__ feat, int D) {
    int side = blockIdx.y;
    int n = side ? g_fCnt : g_aCnt;
    int warp = threadIdx.x >> 5;
    int lane = threadIdx.x & 31;
    int b = blockIdx.x * 8 + warp;
    if (b >= n) return;
    int row = side ? g_fRow[b] : g_aRow[b];
    const float4* src = (const float4*)(feat + (size_t)row * D);
    uint4* dst = (uint4*)((side ? g_F : g_A) + (size_t)b * D);
    int nv = D >> 2;                  // <= 256

    float4 v[8];
    float s = 0.f;
    #pragma unroll
    for (int j = 0; j < 8; j++) {
        int t = lane + j * 32;
        if (t < nv) {
            v[j] = src[t];
            s += v[j].x * v[j].x + v[j].y * v[j].y +
                 v[j].z * v[j].z + v[j].w * v[j].w;
        }
    }
    #pragma unroll
    for (int o = 16; o; o >>= 1) s += __shfl_xor_sync(0xffffffffu, s, o);
    float scale = 1.f / fmaxf(sqrtf(s), 1e-12f);
    #pragma unroll
    for (int j = 0; j < 8; j++) {
        int t = lane + j * 32;
        if (t < nv) {
            uint4 o;
            asm("cvt.rna.tf32.f32 %0, %1;" : "=r"(o.x) : "f"(v[j].x * scale));
            asm("cvt.rna.tf32.f32 %0, %1;" : "=r"(o.y) : "f"(v[j].y * scale));
            asm("cvt.rna.tf32.f32 %0, %1;" : "=r"(o.z) : "f"(v[j].z * scale));
            asm("cvt.rna.tf32.f32 %0, %1;" : "=r"(o.w) : "f"(v[j].w * scale));
            dst[t] = o;
        }
    }
}

// ---- tf32 mma.sync wrapper ------------------------------------------------
__device__ __forceinline__ void mma_tf32(float* d, const uint32_t* a,
                                         const uint32_t* b) {
    asm volatile(
        "mma.sync.aligned.m16n8k8.row.col.f32.tf32.tf32.f32 "
        "{%0,%1,%2,%3}, {%4,%5,%6,%7}, {%8,%9}, {%0,%1,%2,%3};"
        : "+f"(d[0]), "+f"(d[1]), "+f"(d[2]), "+f"(d[3])
        : "r"(a[0]), "r"(a[1]), "r"(a[2]), "r"(a[3]), "r"(b[0]), "r"(b[1]));
}

// ---- K4: 256x128 HMMA tf32 GEMM, cp.async double buffer, fused min -------
// 16 warps: warp grid 4(M)x4(N), warp tile 64x32 = 4x4 m16n8k8 atoms.
#define SA_ELEMS (BM * ASTR)          // 9216 floats
#define SB_ELEMS (BN * ASTR)          // 4608 floats
#define SMEM4_BYTES ((2 * SA_ELEMS + 2 * SB_ELEMS) * 4 + BN * 4)

__global__ void __launch_bounds__(NTHR, 1)
k4_mma_min(int D) {
    extern __shared__ float smem[];
    float* sA = smem;                          // [2][SA_ELEMS]
    float* sB = smem + 2 * SA_ELEMS;           // [2][SB_ELEMS]
    int* sFlab = (int*)(smem + 2 * SA_ELEMS + 2 * SB_ELEMS);

    const int NA = g_aCnt;
    const int NF = g_fCnt;
    const int by = blockIdx.y, bx = blockIdx.x;
    if (by * BM >= NA || bx * BN >= NF) return;

    const int tid = threadIdx.x;
    const int wid = tid >> 5;
    const int lane = tid & 31;
    const int qid = lane >> 2;
    const int qlane = lane & 3;
    const int wm = (wid & 3) * 64;
    const int wn = (wid >> 2) * 32;

    if (tid < BN) {
        int f = bx * BN + tid;
        sFlab[tid] = (f < NF) ? g_fLab[f] : -1;
    }

    const uint32_t sa_base = smem_u32(sA);
    const uint32_t sb_base = smem_u32(sB);

    // per-thread load slots (fixed for all chunks)
    int amRow[4], amQ[4], bmRow[2], bmQ[2];
    const float* aSrc[4];
    const float* bSrc[2];
    #pragma unroll
    for (int it = 0; it < 4; it++) {
        int idx = tid + it * NTHR;          // 0..2047
        amRow[it] = idx >> 3;
        amQ[it] = idx & 7;
        int ga = by * BM + amRow[it];
        if (ga > NA - 1) ga = NA - 1;       // clamp; out-of-range rows unused
        aSrc[it] = &g_A[(size_t)ga * D + amQ[it] * 4];
    }
    #pragma unroll
    for (int it = 0; it < 2; it++) {
        int idx = tid + it * NTHR;          // 0..1023
        bmRow[it] = idx >> 3;
        bmQ[it] = idx & 7;
        int gf = bx * BN + bmRow[it];
        if (gf > NF - 1) gf = NF - 1;       // clamp; excluded via sFlab=-1
        bSrc[it] = &g_F[(size_t)gf * D + bmQ[it] * 4];
    }

    float acc[4][4][4];
    #pragma unroll
    for (int mi = 0; mi < 4; mi++)
        #pragma unroll
        for (int ni = 0; ni < 4; ni++)
            #pragma unroll
            for (int r = 0; r < 4; r++) acc[mi][ni][r] = 0.f;

    const int nch = D >> 5;

    // prefetch chunk 0 into buffer 0
    #pragma unroll
    for (int it = 0; it < 4; it++)
        cpa16(sa_base + (amRow[it] * ASTR + amQ[it] * 4) * 4, aSrc[it]);
    #pragma unroll
    for (int it = 0; it < 2; it++)
        cpa16(sb_base + (bmRow[it] * ASTR + bmQ[it] * 4) * 4, bSrc[it]);
    cpa_commit();

    for (int c = 0; c < nch; c++) {
        const int cur = c & 1;
        if (c + 1 < nch) {
            const int nxt = (c + 1) & 1;
            const int koff = (c + 1) << 5;
            uint32_t saN = sa_base + nxt * (SA_ELEMS * 4);
            uint32_t sbN = sb_base + nxt * (SB_ELEMS * 4);
            #pragma unroll
            for (int it = 0; it < 4; it++)
                cpa16(saN + (amRow[it] * ASTR + amQ[it] * 4) * 4,
                      aSrc[it] + koff);
            #pragma unroll
            for (int it = 0; it < 2; it++)
                cpa16(sbN + (bmRow[it] * ASTR + bmQ[it] * 4) * 4,
                      bSrc[it] + koff);
            cpa_commit();
            asm volatile("cp.async.wait_group 1;");
        } else {
            asm volatile("cp.async.wait_group 0;");
        }
        __syncthreads();

        const float* cA = sA + cur * SA_ELEMS;
        const float* cB = sB + cur * SB_ELEMS;
        #pragma unroll
        for (int g = 0; g < 4; g++) {
            const int kb = g * 8 + qlane;
            uint32_t a[4][4], b[4][2];
            #pragma unroll
            for (int mi = 0; mi < 4; mi++) {
                int r = wm + mi * 16 + qid;
                a[mi][0] = __float_as_uint(cA[r * ASTR + kb]);
                a[mi][1] = __float_as_uint(cA[(r + 8) * ASTR + kb]);
                a[mi][2] = __float_as_uint(cA[r * ASTR + kb + 4]);
                a[mi][3] = __float_as_uint(cA[(r + 8) * ASTR + kb + 4]);
            }
            #pragma unroll
            for (int ni = 0; ni < 4; ni++) {
                int nr = wn + ni * 8 + qid;
                b[ni][0] = __float_as_uint(cB[nr * ASTR + kb]);
                b[ni][1] = __float_as_uint(cB[nr * ASTR + kb + 4]);
            }
            #pragma unroll
            for (int mi = 0; mi < 4; mi++)
                #pragma unroll
                for (int ni = 0; ni < 4; ni++)
                    mma_tf32(acc[mi][ni], a[mi], b[ni]);
        }
        __syncthreads();   // compute done before next iter overwrites buffer
    }

    // --- epilogue: d^2 = max(2 - 2*dot, 0), masked min per anchor row ----
    int al[4][2];
    #pragma unroll
    for (int mi = 0; mi < 4; mi++)
        #pragma unroll
        for (int h = 0; h < 2; h++) {
            int a_ = by * BM + wm + mi * 16 + qid + h * 8;
            al[mi][h] = (a_ < NA) ? g_aLab[a_] : -2;
        }
    float posm[4][2], negm[4][2];
    #pragma unroll
    for (int mi = 0; mi < 4; mi++)
        #pragma unroll
        for (int h = 0; h < 2; h++) {
            posm[mi][h] = __uint_as_float(INFBITS);
            negm[mi][h] = posm[mi][h];
        }

    #pragma unroll
    for (int mi = 0; mi < 4; mi++) {
        #pragma unroll
        for (int ni = 0; ni < 4; ni++) {
            int n0 = wn + ni * 8 + 2 * qlane;
            int fl0 = sFlab[n0];
            int fl1 = sFlab[n0 + 1];
            #pragma unroll
            for (int h = 0; h < 2; h++) {
                float d20 = fmaxf(fmaf(-2.f, acc[mi][ni][h * 2 + 0], 2.f), 0.f);
                float d21 = fmaxf(fmaf(-2.f, acc[mi][ni][h * 2 + 1], 2.f), 0.f);
                int a_l = al[mi][h];
                if (fl0 >= 0) {
                    if (fl0 == a_l) posm[mi][h] = fminf(posm[mi][h], d20);
                    else            negm[mi][h] = fminf(negm[mi][h], d20);
                }
                if (fl1 >= 0) {
                    if (fl1 == a_l) posm[mi][h] = fminf(posm[mi][h], d21);
                    else            negm[mi][h] = fminf(negm[mi][h], d21);
                }
            }
        }
    }
    #pragma unroll
    for (int o = 1; o < 4; o <<= 1) {
        #pragma unroll
        for (int mi = 0; mi < 4; mi++)
            #pragma unroll
            for (int h = 0; h < 2; h++) {
                posm[mi][h] = fminf(posm[mi][h],
                                    __shfl_xor_sync(0xffffffffu, posm[mi][h], o));
                negm[mi][h] = fminf(negm[mi][h],
                                    __shfl_xor_sync(0xffffffffu, negm[mi][h], o));
            }
    }
    if (qlane == 0) {
        #pragma unroll
        for (int mi = 0; mi < 4; mi++)
            #pragma unroll
            for (int h = 0; h < 2; h++) {
                int a_ = by * BM + wm + mi * 16 + qid + h * 8;
                if (a_ < NA) {
                    atomicMin(&g_posBits[a_], __float_as_uint(posm[mi][h]));
                    atomicMin(&g_negBits[a_], __float_as_uint(negm[mi][h]));
                }
            }
    }
}

// ---- K5: finalize --------------------------------------------------------
__global__ void k5_finalize(float* __restrict__ out) {
    int n = g_aCnt;
    int tid = threadIdx.x;
    float sum = 0.f, cnt = 0.f;
    for (int i = tid; i < n; i += blockDim.x) {
        unsigned pb = g_posBits[i];
        unsigned nb = g_negBits[i];
        if (pb < INFBITS && nb < INFBITS) {
            float tl = fmaxf(sqrtf(__uint_as_float(pb)) -
                             sqrtf(__uint_as_float(nb)) + 0.3f, 0.f);
            sum += tl;
            cnt += 1.f;
        }
    }
    __shared__ float rs[8], rc[8];
    #pragma unroll
    for (int o = 16; o; o >>= 1) {
        sum += __shfl_xor_sync(0xffffffffu, sum, o);
        cnt += __shfl_xor_sync(0xffffffffu, cnt, o);
    }
    if ((tid & 31) == 0) { rs[tid >> 5] = sum; rc[tid >> 5] = cnt; }
    __syncthreads();
    if (tid == 0) {
        float s = 0.f, c = 0.f;
        #pragma unroll
        for (int w = 0; w < 8; w++) { s += rs[w]; c += rc[w]; }
        out[0] = (c > 0.f) ? s / fmaxf(c, 1.f) : 0.f;
    }
}

// ---------------------------------------------------------------------------
extern "C" void kernel_launch(void* const* d_in, const int* in_sizes, int n_in,
                              void* d_out, int out_size) {
    const float* feat  = (const float*)d_in[0];
    const void* labels = d_in[1];
    const void* doms   = d_in[2];
    int B = in_sizes[1];
    int D = in_sizes[0] / B;

    static int smem_set = 0;
    if (!smem_set) {
        cudaFuncSetAttribute(k4_mma_min,
                             cudaFuncAttributeMaxDynamicSharedMemorySize,
                             SMEM4_BYTES);
        smem_set = 1;
    }

    k0_reset<<<1, 1>>>();
    k1_init_detect<<<(B + 255) / 256, 256>>>((const unsigned*)labels, B);
    k2_partition<<<(B + 255) / 256, 256>>>(labels, doms, B);
    k3_normalize<<<dim3((B + 7) / 8, 2), 256>>>(feat, D);
    dim3 grid((B + BN - 1) / BN, (B + BM - 1) / BM);  // worst-case NA/NF
    k4_mma_min<<<grid, NTHR, SMEM4_BYTES>>>(D);
    k5_finalize<<<1, 256>>>((float*)d_out);
}

// round 9
// speedup vs baseline: 1.2863x; 1.2863x over previous
#include <cuda_runtime.h>
#include <stdint.h>

// ---------------------------------------------------------------------------
// TripletContrastiveLoss — tf32 mma.sync, 128x128 tile, occ-2, cp.async
// double buffer. (tcgen05 unavailable: bench PTX targets compute_103 w/o 'a'.)
// ---------------------------------------------------------------------------

#define BMAX 8192
#define DMAX 1024
#define INFBITS 0x7f800000u

#define BM 128
#define BN 128
#define BK 32
#define ASTR 36      // smem row stride (floats); frag banks (4*qid+qlane)%32 distinct
#define NTHR 256
#define SAE (BM * ASTR)                    // 4608 floats per buffer
#define SMEM4_BYTES (4 * SAE * 4 + BN * 4) // 2 bufs x (A+B) + labels = 74240 B

__device__ float g_A[(size_t)BMAX * DMAX];   // normalized anchors (tf32-rounded)
__device__ float g_F[(size_t)BMAX * DMAX];   // normalized fields  (tf32-rounded)
__device__ int   g_aRow[BMAX];
__device__ int   g_fRow[BMAX];
__device__ int   g_aLab[BMAX];
__device__ int   g_fLab[BMAX];
__device__ int   g_aCnt;
__device__ int   g_fCnt;
__device__ unsigned g_posBits[BMAX];
__device__ unsigned g_negBits[BMAX];
__device__ int   g_is64;

__device__ __forceinline__ uint32_t smem_u32(const void* p) {
    uint32_t a;
    asm("{ .reg .u64 t; cvta.to.shared.u64 t, %1; cvt.u32.u64 %0, t; }"
        : "=r"(a) : "l"(p));
    return a;
}
__device__ __forceinline__ void cpa16(uint32_t dst, const void* src) {
    asm volatile("cp.async.cg.shared.global [%0], [%1], 16;"
                 :: "r"(dst), "l"(src));
}

// ---- K0: reset scalars --------------------------------------------------
__global__ void k0_reset() {
    g_aCnt = 0;
    g_fCnt = 0;
    g_is64 = 1;
}

// ---- K1: init min arrays + label dtype detection ------------------------
// int64 labels (<2^31): every odd 32-bit word is 0. int32: some odd word !=0.
__global__ void k1_init_detect(const unsigned* __restrict__ labw, int B) {
    int i = blockIdx.x * blockDim.x + threadIdx.x;
    if (i < B) {
        g_posBits[i] = INFBITS;
        g_negBits[i] = INFBITS;
        if ((i & 1) && labw[i] != 0u) g_is64 = 0;
    }
}

// ---- K2: partition into compact anchor/field lists ----------------------
__global__ void k2_partition(const void* __restrict__ labels,
                             const void* __restrict__ doms, int B) {
    int i = blockIdx.x * blockDim.x + threadIdx.x;
    if (i >= B) return;
    int is64 = g_is64;
    long long dom, lab;
    if (is64) {
        dom = ((const long long*)doms)[i];
        lab = ((const long long*)labels)[i];
    } else {
        dom = ((const int*)doms)[i];
        lab = ((const int*)labels)[i];
    }
    if (dom == 0) {
        int p = atomicAdd(&g_aCnt, 1);
        g_aRow[p] = i;
        g_aLab[p] = (int)lab;
    } else if (dom == 1) {
        int p = atomicAdd(&g_fCnt, 1);
        g_fRow[p] = i;
        g_fLab[p] = (int)lab;
    }
}

// ---- K3: normalize + tf32 round, one warp per row ------------------------
__global__ void k3_normalize(const float* __restrict__ feat, int D) {
    int side = blockIdx.y;
    int n = side ? g_fCnt : g_aCnt;
    int warp = threadIdx.x >> 5;
    int lane = threadIdx.x & 31;
    int b = blockIdx.x * 8 + warp;
    if (b >= n) return;
    int row = side ? g_fRow[b] : g_aRow[b];
    const float4* src = (const float4*)(feat + (size_t)row * D);
    uint4* dst = (uint4*)((side ? g_F : g_A) + (size_t)b * D);
    int nv = D >> 2;

    float4 v[8];
    float s = 0.f;
    #pragma unroll
    for (int j = 0; j < 8; j++) {
        int t = lane + j * 32;
        if (t < nv) {
            v[j] = src[t];
            s += v[j].x * v[j].x + v[j].y * v[j].y +
                 v[j].z * v[j].z + v[j].w * v[j].w;
        }
    }
    #pragma unroll
    for (int o = 16; o; o >>= 1) s += __shfl_xor_sync(0xffffffffu, s, o);
    float scale = 1.f / fmaxf(sqrtf(s), 1e-12f);
    #pragma unroll
    for (int j = 0; j < 8; j++) {
        int t = lane + j * 32;
        if (t < nv) {
            uint4 o;
            asm("cvt.rna.tf32.f32 %0, %1;" : "=r"(o.x) : "f"(v[j].x * scale));
            asm("cvt.rna.tf32.f32 %0, %1;" : "=r"(o.y) : "f"(v[j].y * scale));
            asm("cvt.rna.tf32.f32 %0, %1;" : "=r"(o.z) : "f"(v[j].z * scale));
            asm("cvt.rna.tf32.f32 %0, %1;" : "=r"(o.w) : "f"(v[j].w * scale));
            dst[t] = o;
        }
    }
}

// ---- tf32 mma.sync wrapper ------------------------------------------------
__device__ __forceinline__ void mma_tf32(float* d, const uint32_t* a,
                                         const uint32_t* b) {
    asm volatile(
        "mma.sync.aligned.m16n8k8.row.col.f32.tf32.tf32.f32 "
        "{%0,%1,%2,%3}, {%4,%5,%6,%7}, {%8,%9}, {%0,%1,%2,%3};"
        : "+f"(d[0]), "+f"(d[1]), "+f"(d[2]), "+f"(d[3])
        : "r"(a[0]), "r"(a[1]), "r"(a[2]), "r"(a[3]), "r"(b[0]), "r"(b[1]));
}

// ---- K4: 128x128 HMMA tf32 GEMM, cp.async double buffer, fused min -------
// 8 warps: warp grid 2(M)x4(N), warp tile 64x32 = 4x4 m16n8k8 atoms.
__global__ void __launch_bounds__(NTHR, 2)
k4_mma_min(int D) {
    extern __shared__ float smem[];
    float* sA = smem;              // [2][SAE]
    float* sB = smem + 2 * SAE;    // [2][SAE]
    int* sFlab = (int*)(smem + 4 * SAE);

    const int NA = g_aCnt;
    const int NF = g_fCnt;
    const int by = blockIdx.y, bx = blockIdx.x;
    if (by * BM >= NA || bx * BN >= NF) return;

    const int tid = threadIdx.x;
    const int wid = tid >> 5;
    const int lane = tid & 31;
    const int qid = lane >> 2;
    const int qlane = lane & 3;
    const int wm = (wid & 1) * 64;
    const int wn = (wid >> 1) * 32;

    if (tid < BN) {
        int f = bx * BN + tid;
        sFlab[tid] = (f < NF) ? g_fLab[f] : -1;
    }

    // load geometry: thread covers rows m0+32*it (it=0..3), float4 column q
    const int m0 = tid >> 3;        // 0..31
    const int q4 = (tid & 7) * 4;   // 0,4,...,28
    int aRowG[4], bRowG[4];
    #pragma unroll
    for (int it = 0; it < 4; it++) {
        int ga = by * BM + m0 + 32 * it;
        aRowG[it] = (ga < NA) ? ga : NA - 1;   // clamp; rows >= NA unused
        int gf = bx * BN + m0 + 32 * it;
        bRowG[it] = (gf < NF) ? gf : NF - 1;   // clamp; excluded via sFlab
    }
    const uint32_t sa0 = smem_u32(sA);
    const uint32_t sb0 = smem_u32(sB);
    const uint32_t dstOff = (uint32_t)((m0 * ASTR + q4) * 4);

    float acc[4][4][4];
    #pragma unroll
    for (int mi = 0; mi < 4; mi++)
        #pragma unroll
        for (int ni = 0; ni < 4; ni++)
            #pragma unroll
            for (int r = 0; r < 4; r++) acc[mi][ni][r] = 0.f;

    const int nch = D >> 5;

    // prefetch chunk 0 -> buffer 0
    #pragma unroll
    for (int it = 0; it < 4; it++) {
        cpa16(sa0 + dstOff + it * (32 * ASTR * 4),
              &g_A[(size_t)aRowG[it] * D + q4]);
        cpa16(sb0 + dstOff + it * (32 * ASTR * 4),
              &g_F[(size_t)bRowG[it] * D + q4]);
    }
    asm volatile("cp.async.commit_group;");

    for (int c = 0; c < nch; c++) {
        const int cur = c & 1;
        if (c + 1 < nch) {
            const int nb = (c + 1) & 1;
            const int ko = (c + 1) << 5;
            #pragma unroll
            for (int it = 0; it < 4; it++) {
                cpa16(sa0 + nb * (SAE * 4) + dstOff + it * (32 * ASTR * 4),
                      &g_A[(size_t)aRowG[it] * D + q4 + ko]);
                cpa16(sb0 + nb * (SAE * 4) + dstOff + it * (32 * ASTR * 4),
                      &g_F[(size_t)bRowG[it] * D + q4 + ko]);
            }
            asm volatile("cp.async.commit_group;");
            asm volatile("cp.async.wait_group 1;");
        } else {
            asm volatile("cp.async.wait_group 0;");
        }
        __syncthreads();

        const float* cA = sA + cur * SAE;
        const float* cB = sB + cur * SAE;
        #pragma unroll
        for (int g = 0; g < 4; g++) {
            const int kb = g * 8 + qlane;
            uint32_t a[4][4], b[4][2];
            #pragma unroll
            for (int mi = 0; mi < 4; mi++) {
                int r = wm + mi * 16 + qid;
                a[mi][0] = __float_as_uint(cA[r * ASTR + kb]);
                a[mi][1] = __float_as_uint(cA[(r + 8) * ASTR + kb]);
                a[mi][2] = __float_as_uint(cA[r * ASTR + kb + 4]);
                a[mi][3] = __float_as_uint(cA[(r + 8) * ASTR + kb + 4]);
            }
            #pragma unroll
            for (int ni = 0; ni < 4; ni++) {
                int nr = wn + ni * 8 + qid;
                b[ni][0] = __float_as_uint(cB[nr * ASTR + kb]);
                b[ni][1] = __float_as_uint(cB[nr * ASTR + kb + 4]);
            }
            #pragma unroll
            for (int mi = 0; mi < 4; mi++)
                #pragma unroll
                for (int ni = 0; ni < 4; ni++)
                    mma_tf32(acc[mi][ni], a[mi], b[ni]);
        }
        __syncthreads();   // fragment reads done before buffer reuse
    }

    // --- epilogue: d^2 = max(2 - 2*dot, 0), masked min per anchor row ----
    int al[4][2];
    #pragma unroll
    for (int mi = 0; mi < 4; mi++)
        #pragma unroll
        for (int h = 0; h < 2; h++) {
            int a_ = by * BM + wm + mi * 16 + qid + h * 8;
            al[mi][h] = (a_ < NA) ? g_aLab[a_] : -2;
        }
    float posm[4][2], negm[4][2];
    #pragma unroll
    for (int mi = 0; mi < 4; mi++)
        #pragma unroll
        for (int h = 0; h < 2; h++) {
            posm[mi][h] = __uint_as_float(INFBITS);
            negm[mi][h] = posm[mi][h];
        }

    #pragma unroll
    for (int mi = 0; mi < 4; mi++) {
        #pragma unroll
        for (int ni = 0; ni < 4; ni++) {
            int n0 = wn + ni * 8 + 2 * qlane;
            int fl0 = sFlab[n0];
            int fl1 = sFlab[n0 + 1];
            #pragma unroll
            for (int h = 0; h < 2; h++) {
                float d20 = fmaxf(fmaf(-2.f, acc[mi][ni][h * 2 + 0], 2.f), 0.f);
                float d21 = fmaxf(fmaf(-2.f, acc[mi][ni][h * 2 + 1], 2.f), 0.f);
                int a_l = al[mi][h];
                if (fl0 >= 0) {
                    if (fl0 == a_l) posm[mi][h] = fminf(posm[mi][h], d20);
                    else            negm[mi][h] = fminf(negm[mi][h], d20);
                }
                if (fl1 >= 0) {
                    if (fl1 == a_l) posm[mi][h] = fminf(posm[mi][h], d21);
                    else            negm[mi][h] = fminf(negm[mi][h], d21);
                }
            }
        }
    }
    #pragma unroll
    for (int o = 1; o < 4; o <<= 1) {
        #pragma unroll
        for (int mi = 0; mi < 4; mi++)
            #pragma unroll
            for (int h = 0; h < 2; h++) {
                posm[mi][h] = fminf(posm[mi][h],
                                    __shfl_xor_sync(0xffffffffu, posm[mi][h], o));
                negm[mi][h] = fminf(negm[mi][h],
                                    __shfl_xor_sync(0xffffffffu, negm[mi][h], o));
            }
    }
    if (qlane == 0) {
        #pragma unroll
        for (int mi = 0; mi < 4; mi++)
            #pragma unroll
            for (int h = 0; h < 2; h++) {
                int a_ = by * BM + wm + mi * 16 + qid + h * 8;
                if (a_ < NA) {
                    atomicMin(&g_posBits[a_], __float_as_uint(posm[mi][h]));
                    atomicMin(&g_negBits[a_], __float_as_uint(negm[mi][h]));
                }
            }
    }
}

// ---- K5: finalize --------------------------------------------------------
__global__ void k5_finalize(float* __restrict__ out) {
    int n = g_aCnt;
    int tid = threadIdx.x;
    float sum = 0.f, cnt = 0.f;
    for (int i = tid; i < n; i += blockDim.x) {
        unsigned pb = g_posBits[i];
        unsigned nb = g_negBits[i];
        if (pb < INFBITS && nb < INFBITS) {
            float tl = fmaxf(sqrtf(__uint_as_float(pb)) -
                             sqrtf(__uint_as_float(nb)) + 0.3f, 0.f);
            sum += tl;
            cnt += 1.f;
        }
    }
    __shared__ float rs[8], rc[8];
    #pragma unroll
    for (int o = 16; o; o >>= 1) {
        sum += __shfl_xor_sync(0xffffffffu, sum, o);
        cnt += __shfl_xor_sync(0xffffffffu, cnt, o);
    }
    if ((tid & 31) == 0) { rs[tid >> 5] = sum; rc[tid >> 5] = cnt; }
    __syncthreads();
    if (tid == 0) {
        float s = 0.f, c = 0.f;
        #pragma unroll
        for (int w = 0; w < 8; w++) { s += rs[w]; c += rc[w]; }
        out[0] = (c > 0.f) ? s / fmaxf(c, 1.f) : 0.f;
    }
}

// ---------------------------------------------------------------------------
extern "C" void kernel_launch(void* const* d_in, const int* in_sizes, int n_in,
                              void* d_out, int out_size) {
    const float* feat  = (const float*)d_in[0];
    const void* labels = d_in[1];
    const void* doms   = d_in[2];
    int B = in_sizes[1];
    int D = in_sizes[0] / B;

    static int smem_set = 0;
    if (!smem_set) {
        cudaFuncSetAttribute(k4_mma_min,
                             cudaFuncAttributeMaxDynamicSharedMemorySize,
                             SMEM4_BYTES);
        smem_set = 1;
    }

    k0_reset<<<1, 1>>>();
    k1_init_detect<<<(B + 255) / 256, 256>>>((const unsigned*)labels, B);
    k2_partition<<<(B + 255) / 256, 256>>>(labels, doms, B);
    k3_normalize<<<dim3((B + 7) / 8, 2), 256>>>(feat, D);
    dim3 grid((B + BN - 1) / BN, (B + BM - 1) / BM);  // worst-case NA/NF
    k4_mma_min<<<grid, NTHR, SMEM4_BYTES>>>(D);
    k5_finalize<<<1, 256>>>((float*)d_out);
}